// round 1
// baseline (speedup 1.0000x reference)
#include <cuda_runtime.h>
#include <math.h>

#define T_  8
#define NN  10000
#define EE  160000
#define FF  128
#define GG  32
#define CC  10
#define GATE 384

// ---------------- scratch (static __device__ — no allocations allowed) ----------------
__device__ float g_bufA[T_*NN*FF];        // 41 MB
__device__ float g_bufB[T_*NN*FF];        // 41 MB
__device__ int   g_rowptr[T_*(NN+1)];
__device__ int   g_cursor[T_*NN];         // doubles as histogram
__device__ int   g_colidx[T_*EE];
__device__ float g_dinv[T_*NN];
__device__ float g_pool[T_*GG*FF];
__device__ float g_cnt[T_*GG];
__device__ float g_emb[T_*GG*FF];
__device__ float g_gi[T_*GG*GATE];
__device__ float g_outs[T_*GG*FF];
__device__ float g_h[GG*FF];
__device__ float g_WT[4*FF*GATE];         // transposed Wih0, Whh0, Wih1, Whh1

// ---------------- zeroing ----------------
__global__ void zero_main_kernel() {
    int idx = blockIdx.x * blockDim.x + threadIdx.x;
    if (idx < T_*NN)     g_cursor[idx] = 0;
    if (idx < T_*GG*FF)  g_pool[idx]   = 0.f;
    if (idx < T_*GG)     g_cnt[idx]    = 0.f;
}
__global__ void zero_h_kernel() {
    int idx = blockIdx.x * blockDim.x + threadIdx.x;
    if (idx < GG*FF) g_h[idx] = 0.f;
}

// ---------------- CSR build ----------------
__global__ void hist_kernel(const int* __restrict__ ei) {
    int idx = blockIdx.x * blockDim.x + threadIdx.x;
    if (idx >= T_*EE) return;
    int t = idx / EE, e = idx - t*EE;
    int dst = ei[(t*2 + 1)*EE + e];
    atomicAdd(&g_cursor[t*NN + dst], 1);
}

// one block per snapshot: exclusive scan of histogram -> rowptr (+cursor copy) + dinv
__global__ void scan_kernel() {
    int t = blockIdx.x;
    __shared__ int warpsums[32];
    __shared__ int carry_s;
    int tid = threadIdx.x;            // 1024
    int lane = tid & 31, wid = tid >> 5;
    if (tid == 0) carry_s = 0;
    __syncthreads();
    for (int base = 0; base < NN; base += 1024) {
        int i = base + tid;
        int v = (i < NN) ? g_cursor[t*NN + i] : 0;
        int inc = v;
        #pragma unroll
        for (int o = 1; o < 32; o <<= 1) {
            int y = __shfl_up_sync(0xFFFFFFFFu, inc, o);
            if (lane >= o) inc += y;
        }
        if (lane == 31) warpsums[wid] = inc;
        __syncthreads();
        if (wid == 0) {
            int w = warpsums[lane];
            #pragma unroll
            for (int o = 1; o < 32; o <<= 1) {
                int y = __shfl_up_sync(0xFFFFFFFFu, w, o);
                if (lane >= o) w += y;
            }
            warpsums[lane] = w;
        }
        __syncthreads();
        int exc = inc - v + (wid ? warpsums[wid-1] : 0);
        int off = carry_s + exc;
        if (i < NN) {
            g_rowptr[t*(NN+1) + i] = off;
            g_cursor[t*NN + i]     = off;
            g_dinv[t*NN + i]       = rsqrtf((float)v + 1.0f);
        }
        __syncthreads();
        if (tid == 1023) carry_s += warpsums[31];
        __syncthreads();
    }
    if (tid == 0) g_rowptr[t*(NN+1) + NN] = carry_s;
}

__global__ void fill_kernel(const int* __restrict__ ei) {
    int idx = blockIdx.x * blockDim.x + threadIdx.x;
    if (idx >= T_*EE) return;
    int t = idx / EE, e = idx - t*EE;
    int src = ei[(t*2 + 0)*EE + e];
    int dst = ei[(t*2 + 1)*EE + e];
    int pos = atomicAdd(&g_cursor[t*NN + dst], 1);
    g_colidx[t*EE + pos] = src;
}

// ---------------- GEMM: O[M,128] = A[M,128] @ W[128,128] (fp32) ----------------
// block: 256 thr, tile 64 rows x 128 cols, thread tile 4x8. W + X tile in smem (96 KB dyn).
__global__ void gemm128_kernel(const float* __restrict__ A, const float* __restrict__ W,
                               float* __restrict__ O) {
    extern __shared__ float sm[];
    float* Ws = sm;               // 128*128
    float* Xs = sm + FF*FF;       // 64*128
    int tid = threadIdx.x;
    const float4* W4 = (const float4*)W;
    for (int i = tid; i < FF*FF/4; i += 256) ((float4*)Ws)[i] = W4[i];
    size_t row0 = (size_t)blockIdx.x * 64;
    const float4* A4 = (const float4*)(A + row0*FF);
    for (int i = tid; i < 64*FF/4; i += 256) ((float4*)Xs)[i] = A4[i];
    __syncthreads();

    int ty = tid >> 4, tx = tid & 15;
    float acc[4][8];
    #pragma unroll
    for (int i = 0; i < 4; i++)
        #pragma unroll
        for (int j = 0; j < 8; j++) acc[i][j] = 0.f;

    #pragma unroll 4
    for (int k = 0; k < FF; k++) {
        float4 w0 = *(const float4*)&Ws[k*FF + tx*8];
        float4 w1 = *(const float4*)&Ws[k*FF + tx*8 + 4];
        float xv[4];
        #pragma unroll
        for (int i = 0; i < 4; i++) xv[i] = Xs[(ty*4 + i)*FF + k];
        #pragma unroll
        for (int i = 0; i < 4; i++) {
            acc[i][0] += xv[i]*w0.x; acc[i][1] += xv[i]*w0.y;
            acc[i][2] += xv[i]*w0.z; acc[i][3] += xv[i]*w0.w;
            acc[i][4] += xv[i]*w1.x; acc[i][5] += xv[i]*w1.y;
            acc[i][6] += xv[i]*w1.z; acc[i][7] += xv[i]*w1.w;
        }
    }
    #pragma unroll
    for (int i = 0; i < 4; i++) {
        float* orow = O + (row0 + ty*4 + i)*FF + tx*8;
        *(float4*)(orow)     = make_float4(acc[i][0], acc[i][1], acc[i][2], acc[i][3]);
        *(float4*)(orow + 4) = make_float4(acc[i][4], acc[i][5], acc[i][6], acc[i][7]);
    }
}

// ---------------- edge aggregation (one warp per (t, node), CSR gather) ----------------
__global__ void agg_kernel(const float* __restrict__ hin, float* __restrict__ hout,
                           const float* __restrict__ bias) {
    int wid  = (blockIdx.x * blockDim.x + threadIdx.x) >> 5;
    int lane = threadIdx.x & 31;
    if (wid >= T_*NN) return;
    int t = wid / NN, v = wid - t*NN;
    const float* dv_t = g_dinv + t*NN;
    float dv = dv_t[v];
    int beg = g_rowptr[t*(NN+1) + v];
    int end = g_rowptr[t*(NN+1) + v + 1];
    const int*   ci    = g_colidx + t*EE;
    const float* hbase = hin + (size_t)t*NN*FF;
    float4 acc = make_float4(0.f, 0.f, 0.f, 0.f);
    for (int e = beg; e < end; e++) {
        int s = ci[e];
        float c = dv * dv_t[s];
        float4 hv = *(const float4*)(hbase + (size_t)s*FF + lane*4);
        acc.x += c*hv.x; acc.y += c*hv.y; acc.z += c*hv.z; acc.w += c*hv.w;
    }
    {   // self-loop term
        float c = dv*dv;
        float4 hv = *(const float4*)(hbase + (size_t)v*FF + lane*4);
        acc.x += c*hv.x; acc.y += c*hv.y; acc.z += c*hv.z; acc.w += c*hv.w;
    }
    float4 b = *(const float4*)(bias + lane*4);
    acc.x = fmaxf(acc.x + b.x, 0.f);
    acc.y = fmaxf(acc.y + b.y, 0.f);
    acc.z = fmaxf(acc.z + b.z, 0.f);
    acc.w = fmaxf(acc.w + b.w, 0.f);
    *(float4*)(hout + (size_t)t*NN*FF + (size_t)v*FF + lane*4) = acc;
}

// ---------------- pooling ----------------
__global__ void pool_kernel(const float* __restrict__ h, const int* __restrict__ batch) {
    int wid  = (blockIdx.x * blockDim.x + threadIdx.x) >> 5;
    int lane = threadIdx.x & 31;
    if (wid >= T_*NN) return;
    int t = wid / NN, v = wid - t*NN;
    int g = batch[t*NN + v];
    float4 hv = *(const float4*)(h + (size_t)(t*NN + v)*FF + lane*4);
    float* p = g_pool + (t*GG + g)*FF + lane*4;
    atomicAdd(p+0, hv.x); atomicAdd(p+1, hv.y);
    atomicAdd(p+2, hv.z); atomicAdd(p+3, hv.w);
    if (lane == 0) atomicAdd(&g_cnt[t*GG + g], 1.0f);
}

__global__ void emb_kernel() {
    int idx = blockIdx.x * blockDim.x + threadIdx.x;
    if (idx >= T_*GG*FF) return;
    float c = g_cnt[idx / FF];
    g_emb[idx] = g_pool[idx] / fmaxf(c, 1.0f);
}

// ---------------- GRU ----------------
__global__ void transpose384_kernel(const float* __restrict__ W, float* __restrict__ WT) {
    int idx = blockIdx.x * blockDim.x + threadIdx.x;   // over GATE*FF
    if (idx >= GATE*FF) return;
    int j = idx / FF, k = idx - j*FF;
    WT[k*GATE + j] = W[idx];
}

// Gi[m, :] = X[m, :] @ WT + bih   (X: [T*G, 128], WT: [128, 384])
__global__ void gi_kernel(const float* __restrict__ X, const float* __restrict__ WT,
                          const float* __restrict__ bih, float* __restrict__ Gi) {
    int m = blockIdx.x, j = threadIdx.x;   // 384 threads
    __shared__ float xs[FF];
    if (j < FF) xs[j] = X[m*FF + j];
    __syncthreads();
    float acc = bih[j];
    #pragma unroll 4
    for (int k = 0; k < FF; k++) acc += xs[k] * WT[k*GATE + j];
    Gi[m*GATE + j] = acc;
}

__device__ __forceinline__ float sigmoidf_(float x) { return 1.0f / (1.0f + expf(-x)); }

// one step of the GRU cell: 32 blocks (one per graph), 128 threads (hidden dim)
__global__ void gru_step_kernel(const float* __restrict__ WhhT, const float* __restrict__ bhh,
                                const float* __restrict__ gi_t, float* __restrict__ out_t) {
    int g = blockIdx.x, j = threadIdx.x;
    __shared__ float hs[FF];
    hs[j] = g_h[g*FF + j];
    __syncthreads();
    float hr = bhh[j], hz = bhh[FF + j], hn = bhh[2*FF + j];
    #pragma unroll 4
    for (int k = 0; k < FF; k++) {
        float hv = hs[k];
        const float* w = WhhT + k*GATE;
        hr += hv * w[j];
        hz += hv * w[FF + j];
        hn += hv * w[2*FF + j];
    }
    float ir  = gi_t[g*GATE + j];
    float iz  = gi_t[g*GATE + FF + j];
    float inn = gi_t[g*GATE + 2*FF + j];
    float r = sigmoidf_(ir + hr);
    float z = sigmoidf_(iz + hz);
    float n = tanhf(inn + r*hn);
    float hnew = (1.0f - z)*n + z*hs[j];
    g_h[g*FF + j] = hnew;
    if (out_t) out_t[g*FF + j] = hnew;
}

// ---------------- head ----------------
__global__ void final_kernel(const float* __restrict__ Wc, const float* __restrict__ bc,
                             float* __restrict__ out) {
    __shared__ float hs[GG*FF];
    int tid = threadIdx.x;
    for (int i = tid; i < GG*FF; i += blockDim.x) hs[i] = g_h[i];
    __syncthreads();
    if (tid < GG*CC) {
        int g = tid / CC, c = tid - g*CC;
        float acc = bc[c];
        #pragma unroll 4
        for (int k = 0; k < FF; k++) acc += hs[g*FF + k] * Wc[c*FF + k];
        out[tid] = acc;
    }
}

// ---------------- launch ----------------
extern "C" void kernel_launch(void* const* d_in, const int* in_sizes, int n_in,
                              void* d_out, int out_size) {
    const float* x     = (const float*)d_in[0];
    const int*   ei    = (const int*)  d_in[1];
    const int*   batch = (const int*)  d_in[2];
    const float* W1    = (const float*)d_in[3];
    const float* b1    = (const float*)d_in[4];
    const float* W2    = (const float*)d_in[5];
    const float* b2    = (const float*)d_in[6];
    const float* Wih0  = (const float*)d_in[7];
    const float* Whh0  = (const float*)d_in[8];
    const float* bih0  = (const float*)d_in[9];
    const float* bhh0  = (const float*)d_in[10];
    const float* Wih1  = (const float*)d_in[11];
    const float* Whh1  = (const float*)d_in[12];
    const float* bih1  = (const float*)d_in[13];
    const float* bhh1  = (const float*)d_in[14];
    const float* Wc    = (const float*)d_in[15];
    const float* bc    = (const float*)d_in[16];
    float* out = (float*)d_out;

    cudaFuncSetAttribute(gemm128_kernel,
                         cudaFuncAttributeMaxDynamicSharedMemorySize, 98304);

    void* p;
    cudaGetSymbolAddress(&p, g_bufA);  float* bufA = (float*)p;
    cudaGetSymbolAddress(&p, g_bufB);  float* bufB = (float*)p;
    cudaGetSymbolAddress(&p, g_emb);   float* emb  = (float*)p;
    cudaGetSymbolAddress(&p, g_gi);    float* gi   = (float*)p;
    cudaGetSymbolAddress(&p, g_outs);  float* outs = (float*)p;
    cudaGetSymbolAddress(&p, g_WT);    float* wt   = (float*)p;
    float* WT_ih0 = wt + 0*FF*GATE;
    float* WT_hh0 = wt + 1*FF*GATE;
    float* WT_ih1 = wt + 2*FF*GATE;
    float* WT_hh1 = wt + 3*FF*GATE;

    const int ZB = (T_*NN + 255)/256;          // covers all zero targets
    zero_main_kernel<<<ZB, 256>>>();
    hist_kernel<<<(T_*EE + 255)/256, 256>>>(ei);
    scan_kernel<<<T_, 1024>>>();
    fill_kernel<<<(T_*EE + 255)/256, 256>>>(ei);

    // GCN layer 1 (all 8 snapshots batched)
    gemm128_kernel<<<T_*NN/64, 256, 98304>>>(x, W1, bufA);
    agg_kernel<<<(T_*NN*32 + 255)/256, 256>>>(bufA, bufB, b1);
    // GCN layer 2
    gemm128_kernel<<<T_*NN/64, 256, 98304>>>(bufB, W2, bufA);
    agg_kernel<<<(T_*NN*32 + 255)/256, 256>>>(bufA, bufB, b2);

    // mean pool
    pool_kernel<<<(T_*NN*32 + 255)/256, 256>>>(bufB, batch);
    emb_kernel<<<(T_*GG*FF + 255)/256, 256>>>();

    // GRU weight transposes
    transpose384_kernel<<<(GATE*FF + 255)/256, 256>>>(Wih0, WT_ih0);
    transpose384_kernel<<<(GATE*FF + 255)/256, 256>>>(Whh0, WT_hh0);
    transpose384_kernel<<<(GATE*FF + 255)/256, 256>>>(Wih1, WT_ih1);
    transpose384_kernel<<<(GATE*FF + 255)/256, 256>>>(Whh1, WT_hh1);

    // GRU layer 0
    gi_kernel<<<T_*GG, GATE>>>(emb, WT_ih0, bih0, gi);
    zero_h_kernel<<<(GG*FF + 255)/256, 256>>>();
    for (int t = 0; t < T_; t++)
        gru_step_kernel<<<GG, FF>>>(WT_hh0, bhh0, gi + t*GG*GATE, outs + t*GG*FF);

    // GRU layer 1
    gi_kernel<<<T_*GG, GATE>>>(outs, WT_ih1, bih1, gi);
    zero_h_kernel<<<(GG*FF + 255)/256, 256>>>();
    for (int t = 0; t < T_; t++)
        gru_step_kernel<<<GG, FF>>>(WT_hh1, bhh1, gi + t*GG*GATE, (float*)0);

    // head
    final_kernel<<<1, 512>>>(Wc, bc, out);
}

// round 2
// speedup vs baseline: 1.5350x; 1.5350x over previous
#include <cuda_runtime.h>
#include <math.h>

#define T_  8
#define NN  10000
#define EE  160000
#define FF  128
#define GG  32
#define CC  10
#define GATE 384

// ---------------- scratch (static __device__ — no allocations allowed) ----------------
__device__ __align__(16) float g_bufA[T_*NN*FF];        // 41 MB
__device__ __align__(16) float g_bufB[T_*NN*FF];        // 41 MB
__device__ int   g_rowptr[T_*(NN+1)];
__device__ int   g_cursor[T_*NN];         // doubles as histogram
__device__ int   g_colidx[T_*EE];
__device__ float g_dinv[T_*NN];
__device__ __align__(16) float g_pool[T_*GG*FF];
__device__ int   g_cntI[T_*GG];

// ---------------- zeroing ----------------
__global__ void zero_main_kernel() {
    int idx = blockIdx.x * blockDim.x + threadIdx.x;
    if (idx < T_*NN)     g_cursor[idx] = 0;
    if (idx < T_*GG*FF)  g_pool[idx]   = 0.f;
    if (idx < T_*GG)     g_cntI[idx]   = 0;
}

// ---------------- CSR build + batch counts ----------------
__global__ void hist_count_kernel(const int* __restrict__ ei, const int* __restrict__ batch) {
    int idx = blockIdx.x * blockDim.x + threadIdx.x;
    if (idx < T_*EE) {
        int t = idx / EE, e = idx - t*EE;
        int dst = ei[(t*2 + 1)*EE + e];
        atomicAdd(&g_cursor[t*NN + dst], 1);
    }
    if (idx < T_*NN) {
        int t = idx / NN;
        int g = batch[idx];
        atomicAdd(&g_cntI[t*GG + g], 1);
    }
}

// one block per snapshot: exclusive scan of histogram -> rowptr (+cursor copy) + dinv
__global__ void scan_kernel() {
    int t = blockIdx.x;
    __shared__ int warpsums[32];
    __shared__ int carry_s;
    int tid = threadIdx.x;            // 1024
    int lane = tid & 31, wid = tid >> 5;
    if (tid == 0) carry_s = 0;
    __syncthreads();
    for (int base = 0; base < NN; base += 1024) {
        int i = base + tid;
        int v = (i < NN) ? g_cursor[t*NN + i] : 0;
        int inc = v;
        #pragma unroll
        for (int o = 1; o < 32; o <<= 1) {
            int y = __shfl_up_sync(0xFFFFFFFFu, inc, o);
            if (lane >= o) inc += y;
        }
        if (lane == 31) warpsums[wid] = inc;
        __syncthreads();
        if (wid == 0) {
            int w = warpsums[lane];
            #pragma unroll
            for (int o = 1; o < 32; o <<= 1) {
                int y = __shfl_up_sync(0xFFFFFFFFu, w, o);
                if (lane >= o) w += y;
            }
            warpsums[lane] = w;
        }
        __syncthreads();
        int exc = inc - v + (wid ? warpsums[wid-1] : 0);
        int off = carry_s + exc;
        if (i < NN) {
            g_rowptr[t*(NN+1) + i] = off;
            g_cursor[t*NN + i]     = off;
            g_dinv[t*NN + i]       = rsqrtf((float)v + 1.0f);
        }
        __syncthreads();
        if (tid == 1023) carry_s += warpsums[31];
        __syncthreads();
    }
    if (tid == 0) g_rowptr[t*(NN+1) + NN] = carry_s;
}

__global__ void fill_kernel(const int* __restrict__ ei) {
    int idx = blockIdx.x * blockDim.x + threadIdx.x;
    if (idx >= T_*EE) return;
    int t = idx / EE, e = idx - t*EE;
    int src = ei[(t*2 + 0)*EE + e];
    int dst = ei[(t*2 + 1)*EE + e];
    int pos = atomicAdd(&g_cursor[t*NN + dst], 1);
    g_colidx[t*EE + pos] = src;
}

// ---------------- GEMM: O[M,128] = A[M,128] @ W[128,128] (fp32) ----------------
__global__ void gemm128_kernel(const float* __restrict__ A, const float* __restrict__ W,
                               float* __restrict__ O) {
    extern __shared__ float sm[];
    float* Ws = sm;               // 128*128
    float* Xs = sm + FF*FF;       // 64*128
    int tid = threadIdx.x;
    const float4* W4 = (const float4*)W;
    for (int i = tid; i < FF*FF/4; i += 256) ((float4*)Ws)[i] = W4[i];
    size_t row0 = (size_t)blockIdx.x * 64;
    const float4* A4 = (const float4*)(A + row0*FF);
    for (int i = tid; i < 64*FF/4; i += 256) ((float4*)Xs)[i] = A4[i];
    __syncthreads();

    int ty = tid >> 4, tx = tid & 15;
    float acc[4][8];
    #pragma unroll
    for (int i = 0; i < 4; i++)
        #pragma unroll
        for (int j = 0; j < 8; j++) acc[i][j] = 0.f;

    #pragma unroll 4
    for (int k = 0; k < FF; k++) {
        float4 w0 = *(const float4*)&Ws[k*FF + tx*8];
        float4 w1 = *(const float4*)&Ws[k*FF + tx*8 + 4];
        float xv[4];
        #pragma unroll
        for (int i = 0; i < 4; i++) xv[i] = Xs[(ty*4 + i)*FF + k];
        #pragma unroll
        for (int i = 0; i < 4; i++) {
            acc[i][0] += xv[i]*w0.x; acc[i][1] += xv[i]*w0.y;
            acc[i][2] += xv[i]*w0.z; acc[i][3] += xv[i]*w0.w;
            acc[i][4] += xv[i]*w1.x; acc[i][5] += xv[i]*w1.y;
            acc[i][6] += xv[i]*w1.z; acc[i][7] += xv[i]*w1.w;
        }
    }
    #pragma unroll
    for (int i = 0; i < 4; i++) {
        float* orow = O + (row0 + ty*4 + i)*FF + tx*8;
        *(float4*)(orow)     = make_float4(acc[i][0], acc[i][1], acc[i][2], acc[i][3]);
        *(float4*)(orow + 4) = make_float4(acc[i][4], acc[i][5], acc[i][6], acc[i][7]);
    }
}

// ---------------- shared edge-gather body (one warp per (t,node)) ----------------
__device__ __forceinline__ float4 gather_node(const float* __restrict__ hbase,
                                              const float* __restrict__ dv_t,
                                              const int* __restrict__ ci,
                                              int beg, int end, int v, float dv, int lane) {
    float4 acc = make_float4(0.f, 0.f, 0.f, 0.f);
    int e = beg;
    for (; e + 4 <= end; e += 4) {
        int s0 = ci[e], s1 = ci[e+1], s2 = ci[e+2], s3 = ci[e+3];
        float c0 = dv * dv_t[s0], c1 = dv * dv_t[s1];
        float c2 = dv * dv_t[s2], c3 = dv * dv_t[s3];
        float4 a0 = *(const float4*)(hbase + (size_t)s0*FF + lane*4);
        float4 a1 = *(const float4*)(hbase + (size_t)s1*FF + lane*4);
        float4 a2 = *(const float4*)(hbase + (size_t)s2*FF + lane*4);
        float4 a3 = *(const float4*)(hbase + (size_t)s3*FF + lane*4);
        acc.x += c0*a0.x + c1*a1.x + c2*a2.x + c3*a3.x;
        acc.y += c0*a0.y + c1*a1.y + c2*a2.y + c3*a3.y;
        acc.z += c0*a0.z + c1*a1.z + c2*a2.z + c3*a3.z;
        acc.w += c0*a0.w + c1*a1.w + c2*a2.w + c3*a3.w;
    }
    for (; e < end; e++) {
        int s = ci[e];
        float c = dv * dv_t[s];
        float4 hv = *(const float4*)(hbase + (size_t)s*FF + lane*4);
        acc.x += c*hv.x; acc.y += c*hv.y; acc.z += c*hv.z; acc.w += c*hv.w;
    }
    {   // self-loop
        float c = dv*dv;
        float4 hv = *(const float4*)(hbase + (size_t)v*FF + lane*4);
        acc.x += c*hv.x; acc.y += c*hv.y; acc.z += c*hv.z; acc.w += c*hv.w;
    }
    return acc;
}

// layer-1 aggregation: write full node features
__global__ void agg_kernel(const float* __restrict__ hin, float* __restrict__ hout,
                           const float* __restrict__ bias) {
    int wid  = (blockIdx.x * blockDim.x + threadIdx.x) >> 5;
    int lane = threadIdx.x & 31;
    if (wid >= T_*NN) return;
    int t = wid / NN, v = wid - t*NN;
    const float* dv_t = g_dinv + t*NN;
    float dv = dv_t[v];
    int beg = g_rowptr[t*(NN+1) + v];
    int end = g_rowptr[t*(NN+1) + v + 1];
    float4 acc = gather_node(hin + (size_t)t*NN*FF, dv_t, g_colidx + t*EE, beg, end, v, dv, lane);
    float4 b = *(const float4*)(bias + lane*4);
    acc.x = fmaxf(acc.x + b.x, 0.f);
    acc.y = fmaxf(acc.y + b.y, 0.f);
    acc.z = fmaxf(acc.z + b.z, 0.f);
    acc.w = fmaxf(acc.w + b.w, 0.f);
    *(float4*)(hout + (size_t)t*NN*FF + (size_t)v*FF + lane*4) = acc;
}

// layer-2 aggregation fused with mean-pool accumulation (vector float atomics)
__global__ void agg_pool_kernel(const float* __restrict__ hin,
                                const float* __restrict__ bias,
                                const int* __restrict__ batch) {
    int wid  = (blockIdx.x * blockDim.x + threadIdx.x) >> 5;
    int lane = threadIdx.x & 31;
    if (wid >= T_*NN) return;
    int t = wid / NN, v = wid - t*NN;
    const float* dv_t = g_dinv + t*NN;
    float dv = dv_t[v];
    int beg = g_rowptr[t*(NN+1) + v];
    int end = g_rowptr[t*(NN+1) + v + 1];
    float4 acc = gather_node(hin + (size_t)t*NN*FF, dv_t, g_colidx + t*EE, beg, end, v, dv, lane);
    float4 b = *(const float4*)(bias + lane*4);
    acc.x = fmaxf(acc.x + b.x, 0.f);
    acc.y = fmaxf(acc.y + b.y, 0.f);
    acc.z = fmaxf(acc.z + b.z, 0.f);
    acc.w = fmaxf(acc.w + b.w, 0.f);
    int g = batch[t*NN + v];
    float* p = g_pool + (size_t)(t*GG + g)*FF + lane*4;
    asm volatile("red.global.add.v4.f32 [%0], {%1, %2, %3, %4};"
                 :: "l"(p), "f"(acc.x), "f"(acc.y), "f"(acc.z), "f"(acc.w) : "memory");
}

// ---------------- fused GRU (both layers, all steps, gi precompute, head) ----------------
__device__ __forceinline__ float sigmoidf_(float x) { return 1.0f / (1.0f + expf(-x)); }

__global__ __launch_bounds__(GATE, 1)
void gru_fused_kernel(const float* __restrict__ Wih0, const float* __restrict__ Whh0,
                      const float* __restrict__ bih0, const float* __restrict__ bhh0,
                      const float* __restrict__ Wih1, const float* __restrict__ Whh1,
                      const float* __restrict__ bih1, const float* __restrict__ bhh1,
                      const float* __restrict__ Wc,   const float* __restrict__ bc,
                      float* __restrict__ out) {
    int g = blockIdx.x;        // one block per graph
    int j = threadIdx.x;       // gate index 0..383

    __shared__ float emb_s[T_][FF];
    __shared__ float gi_s[T_][GATE];
    __shared__ float outs_s[T_][FF];
    __shared__ float h_s[FF];
    __shared__ float gates_s[GATE];

    // emb = pool / cnt
    for (int i = j; i < T_*FF; i += GATE) {
        int t = i / FF, f = i - t*FF;
        float c = (float)g_cntI[t*GG + g];
        emb_s[t][f] = g_pool[(size_t)(t*GG + g)*FF + f] / fmaxf(c, 1.0f);
    }
    __syncthreads();

    float4 w4[32];

    // Phase A: gi0[t][j] = bih0[j] + emb[t] . Wih0[j,:]
    {
        const float4* wr = (const float4*)(Wih0 + (size_t)j*FF);
        #pragma unroll
        for (int i = 0; i < 32; i++) w4[i] = wr[i];
        float bj = bih0[j];
        #pragma unroll
        for (int t = 0; t < T_; t++) {
            const float4* e4 = (const float4*)emb_s[t];
            float acc = bj;
            #pragma unroll
            for (int i = 0; i < 32; i++) {
                float4 ev = e4[i];
                acc += w4[i].x*ev.x + w4[i].y*ev.y + w4[i].z*ev.z + w4[i].w*ev.w;
            }
            gi_s[t][j] = acc;
        }
    }
    if (j < FF) h_s[j] = 0.f;
    __syncthreads();

    // Phase B: layer-0 recurrence
    {
        const float4* wr = (const float4*)(Whh0 + (size_t)j*FF);
        #pragma unroll
        for (int i = 0; i < 32; i++) w4[i] = wr[i];
        float bj = bhh0[j];
        for (int t = 0; t < T_; t++) {
            const float4* h4 = (const float4*)h_s;
            float acc = bj;
            #pragma unroll
            for (int i = 0; i < 32; i++) {
                float4 hv = h4[i];
                acc += w4[i].x*hv.x + w4[i].y*hv.y + w4[i].z*hv.z + w4[i].w*hv.w;
            }
            gates_s[j] = acc;
            __syncthreads();
            if (j < FF) {
                float r = sigmoidf_(gi_s[t][j]        + gates_s[j]);
                float z = sigmoidf_(gi_s[t][FF+j]     + gates_s[FF+j]);
                float n = tanhf   (gi_s[t][2*FF+j]    + r*gates_s[2*FF+j]);
                float hn = (1.0f - z)*n + z*h_s[j];
                h_s[j] = hn;
                outs_s[t][j] = hn;
            }
            __syncthreads();
        }
    }

    // Phase C: gi1[t][j] = bih1[j] + outs[t] . Wih1[j,:]
    {
        const float4* wr = (const float4*)(Wih1 + (size_t)j*FF);
        #pragma unroll
        for (int i = 0; i < 32; i++) w4[i] = wr[i];
        float bj = bih1[j];
        #pragma unroll
        for (int t = 0; t < T_; t++) {
            const float4* o4 = (const float4*)outs_s[t];
            float acc = bj;
            #pragma unroll
            for (int i = 0; i < 32; i++) {
                float4 ov = o4[i];
                acc += w4[i].x*ov.x + w4[i].y*ov.y + w4[i].z*ov.z + w4[i].w*ov.w;
            }
            gi_s[t][j] = acc;
        }
    }
    __syncthreads();          // gi_s rewrite complete before phase D reads
    if (j < FF) h_s[j] = 0.f;
    __syncthreads();

    // Phase D: layer-1 recurrence
    {
        const float4* wr = (const float4*)(Whh1 + (size_t)j*FF);
        #pragma unroll
        for (int i = 0; i < 32; i++) w4[i] = wr[i];
        float bj = bhh1[j];
        for (int t = 0; t < T_; t++) {
            const float4* h4 = (const float4*)h_s;
            float acc = bj;
            #pragma unroll
            for (int i = 0; i < 32; i++) {
                float4 hv = h4[i];
                acc += w4[i].x*hv.x + w4[i].y*hv.y + w4[i].z*hv.z + w4[i].w*hv.w;
            }
            gates_s[j] = acc;
            __syncthreads();
            if (j < FF) {
                float r = sigmoidf_(gi_s[t][j]     + gates_s[j]);
                float z = sigmoidf_(gi_s[t][FF+j]  + gates_s[FF+j]);
                float n = tanhf   (gi_s[t][2*FF+j] + r*gates_s[2*FF+j]);
                h_s[j] = (1.0f - z)*n + z*h_s[j];
            }
            __syncthreads();
        }
    }

    // Phase E: head  out[g][c] = bc[c] + h . Wc[c,:]
    if (j < CC) {
        const float* wc = Wc + (size_t)j*FF;
        float acc = bc[j];
        #pragma unroll 4
        for (int k = 0; k < FF; k++) acc += h_s[k] * wc[k];
        out[g*CC + j] = acc;
    }
}

// ---------------- launch ----------------
extern "C" void kernel_launch(void* const* d_in, const int* in_sizes, int n_in,
                              void* d_out, int out_size) {
    const float* x     = (const float*)d_in[0];
    const int*   ei    = (const int*)  d_in[1];
    const int*   batch = (const int*)  d_in[2];
    const float* W1    = (const float*)d_in[3];
    const float* b1    = (const float*)d_in[4];
    const float* W2    = (const float*)d_in[5];
    const float* b2    = (const float*)d_in[6];
    const float* Wih0  = (const float*)d_in[7];
    const float* Whh0  = (const float*)d_in[8];
    const float* bih0  = (const float*)d_in[9];
    const float* bhh0  = (const float*)d_in[10];
    const float* Wih1  = (const float*)d_in[11];
    const float* Whh1  = (const float*)d_in[12];
    const float* bih1  = (const float*)d_in[13];
    const float* bhh1  = (const float*)d_in[14];
    const float* Wc    = (const float*)d_in[15];
    const float* bc    = (const float*)d_in[16];
    float* out = (float*)d_out;

    cudaFuncSetAttribute(gemm128_kernel,
                         cudaFuncAttributeMaxDynamicSharedMemorySize, 98304);

    void* p;
    cudaGetSymbolAddress(&p, g_bufA);  float* bufA = (float*)p;
    cudaGetSymbolAddress(&p, g_bufB);  float* bufB = (float*)p;

    zero_main_kernel<<<(T_*NN + 255)/256, 256>>>();
    hist_count_kernel<<<(T_*EE + 255)/256, 256>>>(ei, batch);
    scan_kernel<<<T_, 1024>>>();
    fill_kernel<<<(T_*EE + 255)/256, 256>>>(ei);

    // GCN layer 1 (all 8 snapshots batched)
    gemm128_kernel<<<T_*NN/64, 256, 98304>>>(x, W1, bufA);
    agg_kernel<<<(T_*NN*32 + 255)/256, 256>>>(bufA, bufB, b1);
    // GCN layer 2 + fused mean-pool accumulation
    gemm128_kernel<<<T_*NN/64, 256, 98304>>>(bufB, W2, bufA);
    agg_pool_kernel<<<(T_*NN*32 + 255)/256, 256>>>(bufA, b2, batch);

    // fused GRU (2 layers × 8 steps) + head, one launch
    gru_fused_kernel<<<GG, GATE>>>(Wih0, Whh0, bih0, bhh0,
                                   Wih1, Whh1, bih1, bhh1, Wc, bc, out);
}

// round 4
// speedup vs baseline: 1.7157x; 1.1177x over previous
#include <cuda_runtime.h>
#include <cuda_fp16.h>
#include <math.h>

#define T_  8
#define NN  10000
#define EE  160000
#define FF  128
#define GG  32
#define CC  10
#define GATE 384

// ---------------- scratch (static __device__ — no allocations allowed) ----------------
__device__ __align__(16) __half g_bufA[T_*NN*FF];   // fp16 node features
__device__ __align__(16) __half g_bufB[T_*NN*FF];
__device__ int   g_rowptr[T_*(NN+1)];
__device__ int   g_cursor[T_*NN];
__device__ int   g_colidx[T_*EE];
__device__ float g_dinv[T_*NN];
__device__ __align__(16) float g_pool[T_*GG*FF];
__device__ int   g_cntI[T_*GG];

// ---------------- zeroing ----------------
__global__ void zero_main_kernel() {
    int idx = blockIdx.x * blockDim.x + threadIdx.x;
    if (idx < T_*NN)     g_cursor[idx] = 0;
    if (idx < T_*GG*FF)  g_pool[idx]   = 0.f;
    if (idx < T_*GG)     g_cntI[idx]   = 0;
}

// ---------------- CSR build + batch counts ----------------
__global__ void hist_count_kernel(const int* __restrict__ ei, const int* __restrict__ batch) {
    int idx = blockIdx.x * blockDim.x + threadIdx.x;
    if (idx < T_*EE) {
        int t = idx / EE, e = idx - t*EE;
        int dst = ei[(t*2 + 1)*EE + e];
        atomicAdd(&g_cursor[t*NN + dst], 1);
    }
    if (idx < T_*NN) {
        int t = idx / NN;
        int g = batch[idx];
        atomicAdd(&g_cntI[t*GG + g], 1);
    }
}

__global__ void scan_kernel() {
    int t = blockIdx.x;
    __shared__ int warpsums[32];
    __shared__ int carry_s;
    int tid = threadIdx.x;            // 1024
    int lane = tid & 31, wid = tid >> 5;
    if (tid == 0) carry_s = 0;
    __syncthreads();
    for (int base = 0; base < NN; base += 1024) {
        int i = base + tid;
        int v = (i < NN) ? g_cursor[t*NN + i] : 0;
        int inc = v;
        #pragma unroll
        for (int o = 1; o < 32; o <<= 1) {
            int y = __shfl_up_sync(0xFFFFFFFFu, inc, o);
            if (lane >= o) inc += y;
        }
        if (lane == 31) warpsums[wid] = inc;
        __syncthreads();
        if (wid == 0) {
            int w = warpsums[lane];
            #pragma unroll
            for (int o = 1; o < 32; o <<= 1) {
                int y = __shfl_up_sync(0xFFFFFFFFu, w, o);
                if (lane >= o) w += y;
            }
            warpsums[lane] = w;
        }
        __syncthreads();
        int exc = inc - v + (wid ? warpsums[wid-1] : 0);
        int off = carry_s + exc;
        if (i < NN) {
            g_rowptr[t*(NN+1) + i] = off;
            g_cursor[t*NN + i]     = off;
            g_dinv[t*NN + i]       = rsqrtf((float)v + 1.0f);
        }
        __syncthreads();
        if (tid == 1023) carry_s += warpsums[31];
        __syncthreads();
    }
    if (tid == 0) g_rowptr[t*(NN+1) + NN] = carry_s;
}

__global__ void fill_kernel(const int* __restrict__ ei) {
    int idx = blockIdx.x * blockDim.x + threadIdx.x;
    if (idx >= T_*EE) return;
    int t = idx / EE, e = idx - t*EE;
    int src = ei[(t*2 + 0)*EE + e];
    int dst = ei[(t*2 + 1)*EE + e];
    int pos = atomicAdd(&g_cursor[t*NN + dst], 1);
    g_colidx[t*EE + pos] = src;
}

// ---------------- GEMM: O[M,128](fp16) = A[M,128] @ W[128,128], A fp32 or fp16 ----------------
template<typename TA>
__global__ void gemm128_kernel(const TA* __restrict__ A, const float* __restrict__ W,
                               __half* __restrict__ O) {
    extern __shared__ float sm[];
    float* Ws = sm;               // 128*128 fp32
    float* Xs = sm + FF*FF;       // 64*128 fp32
    int tid = threadIdx.x;
    const float4* W4 = (const float4*)W;
    for (int i = tid; i < FF*FF/4; i += 256) ((float4*)Ws)[i] = W4[i];
    size_t row0 = (size_t)blockIdx.x * 64;

    if constexpr (sizeof(TA) == 4) {
        const float4* A4 = (const float4*)((const float*)A + row0*FF);
        for (int i = tid; i < 64*FF/4; i += 256) ((float4*)Xs)[i] = A4[i];
    } else {
        const uint4* A8 = (const uint4*)((const __half*)A + row0*FF);
        for (int i = tid; i < 64*FF/8; i += 256) {
            uint4 u = A8[i];
            const __half2* hp = (const __half2*)&u;
            float2 f0 = __half22float2(hp[0]);
            float2 f1 = __half22float2(hp[1]);
            float2 f2 = __half22float2(hp[2]);
            float2 f3 = __half22float2(hp[3]);
            ((float4*)Xs)[i*2]   = make_float4(f0.x, f0.y, f1.x, f1.y);
            ((float4*)Xs)[i*2+1] = make_float4(f2.x, f2.y, f3.x, f3.y);
        }
    }
    __syncthreads();

    int ty = tid >> 4, tx = tid & 15;
    float acc[4][8];
    #pragma unroll
    for (int i = 0; i < 4; i++)
        #pragma unroll
        for (int j = 0; j < 8; j++) acc[i][j] = 0.f;

    #pragma unroll 4
    for (int k = 0; k < FF; k++) {
        float4 w0 = *(const float4*)&Ws[k*FF + tx*8];
        float4 w1 = *(const float4*)&Ws[k*FF + tx*8 + 4];
        float xv[4];
        #pragma unroll
        for (int i = 0; i < 4; i++) xv[i] = Xs[(ty*4 + i)*FF + k];
        #pragma unroll
        for (int i = 0; i < 4; i++) {
            acc[i][0] += xv[i]*w0.x; acc[i][1] += xv[i]*w0.y;
            acc[i][2] += xv[i]*w0.z; acc[i][3] += xv[i]*w0.w;
            acc[i][4] += xv[i]*w1.x; acc[i][5] += xv[i]*w1.y;
            acc[i][6] += xv[i]*w1.z; acc[i][7] += xv[i]*w1.w;
        }
    }
    #pragma unroll
    for (int i = 0; i < 4; i++) {
        __half2 h0 = __floats2half2_rn(acc[i][0], acc[i][1]);
        __half2 h1 = __floats2half2_rn(acc[i][2], acc[i][3]);
        __half2 h2 = __floats2half2_rn(acc[i][4], acc[i][5]);
        __half2 h3 = __floats2half2_rn(acc[i][6], acc[i][7]);
        uint4 u;
        u.x = *(unsigned*)&h0; u.y = *(unsigned*)&h1;
        u.z = *(unsigned*)&h2; u.w = *(unsigned*)&h3;
        *(uint4*)(O + (row0 + ty*4 + i)*FF + tx*8) = u;
    }
}

// ---------------- shared edge-gather body (one warp per (t,node)), fp16 rows ----------------
__device__ __forceinline__ float4 ld_h4(const __half* __restrict__ p) {
    uint2 u = *(const uint2*)p;
    float2 a = __half22float2(*(const __half2*)&u.x);
    float2 b = __half22float2(*(const __half2*)&u.y);
    return make_float4(a.x, a.y, b.x, b.y);
}

__device__ __forceinline__ float4 gather_node(const __half* __restrict__ hbase,
                                              const float* __restrict__ dv_t,
                                              const int* __restrict__ ci,
                                              int beg, int end, int v, float dv, int lane) {
    float4 acc = make_float4(0.f, 0.f, 0.f, 0.f);
    int e = beg;
    for (; e + 4 <= end; e += 4) {
        int s0 = ci[e], s1 = ci[e+1], s2 = ci[e+2], s3 = ci[e+3];
        float c0 = dv * dv_t[s0], c1 = dv * dv_t[s1];
        float c2 = dv * dv_t[s2], c3 = dv * dv_t[s3];
        float4 a0 = ld_h4(hbase + (size_t)s0*FF + lane*4);
        float4 a1 = ld_h4(hbase + (size_t)s1*FF + lane*4);
        float4 a2 = ld_h4(hbase + (size_t)s2*FF + lane*4);
        float4 a3 = ld_h4(hbase + (size_t)s3*FF + lane*4);
        acc.x += c0*a0.x + c1*a1.x + c2*a2.x + c3*a3.x;
        acc.y += c0*a0.y + c1*a1.y + c2*a2.y + c3*a3.y;
        acc.z += c0*a0.z + c1*a1.z + c2*a2.z + c3*a3.z;
        acc.w += c0*a0.w + c1*a1.w + c2*a2.w + c3*a3.w;
    }
    for (; e < end; e++) {
        int s = ci[e];
        float c = dv * dv_t[s];
        float4 hv = ld_h4(hbase + (size_t)s*FF + lane*4);
        acc.x += c*hv.x; acc.y += c*hv.y; acc.z += c*hv.z; acc.w += c*hv.w;
    }
    {   // self-loop
        float c = dv*dv;
        float4 hv = ld_h4(hbase + (size_t)v*FF + lane*4);
        acc.x += c*hv.x; acc.y += c*hv.y; acc.z += c*hv.z; acc.w += c*hv.w;
    }
    return acc;
}

// layer-1 aggregation: write full node features (fp16)
__global__ void agg_kernel(const __half* __restrict__ hin, __half* __restrict__ hout,
                           const float* __restrict__ bias) {
    int wid  = (blockIdx.x * blockDim.x + threadIdx.x) >> 5;
    int lane = threadIdx.x & 31;
    if (wid >= T_*NN) return;
    int t = wid / NN, v = wid - t*NN;
    const float* dv_t = g_dinv + t*NN;
    float dv = dv_t[v];
    int beg = g_rowptr[t*(NN+1) + v];
    int end = g_rowptr[t*(NN+1) + v + 1];
    float4 acc = gather_node(hin + (size_t)t*NN*FF, dv_t, g_colidx + t*EE, beg, end, v, dv, lane);
    float4 b = *(const float4*)(bias + lane*4);
    acc.x = fmaxf(acc.x + b.x, 0.f);
    acc.y = fmaxf(acc.y + b.y, 0.f);
    acc.z = fmaxf(acc.z + b.z, 0.f);
    acc.w = fmaxf(acc.w + b.w, 0.f);
    __half2 h0 = __floats2half2_rn(acc.x, acc.y);
    __half2 h1 = __floats2half2_rn(acc.z, acc.w);
    uint2 u; u.x = *(unsigned*)&h0; u.y = *(unsigned*)&h1;
    *(uint2*)(hout + (size_t)t*NN*FF + (size_t)v*FF + lane*4) = u;
}

// layer-2 aggregation fused with mean-pool accumulation (vector fp32 red atomics)
__global__ void agg_pool_kernel(const __half* __restrict__ hin,
                                const float* __restrict__ bias,
                                const int* __restrict__ batch) {
    int wid  = (blockIdx.x * blockDim.x + threadIdx.x) >> 5;
    int lane = threadIdx.x & 31;
    if (wid >= T_*NN) return;
    int t = wid / NN, v = wid - t*NN;
    const float* dv_t = g_dinv + t*NN;
    float dv = dv_t[v];
    int beg = g_rowptr[t*(NN+1) + v];
    int end = g_rowptr[t*(NN+1) + v + 1];
    float4 acc = gather_node(hin + (size_t)t*NN*FF, dv_t, g_colidx + t*EE, beg, end, v, dv, lane);
    float4 b = *(const float4*)(bias + lane*4);
    acc.x = fmaxf(acc.x + b.x, 0.f);
    acc.y = fmaxf(acc.y + b.y, 0.f);
    acc.z = fmaxf(acc.z + b.z, 0.f);
    acc.w = fmaxf(acc.w + b.w, 0.f);
    int g = batch[t*NN + v];
    float* p = g_pool + (size_t)(t*GG + g)*FF + lane*4;
    asm volatile("red.global.add.v4.f32 [%0], {%1, %2, %3, %4};"
                 :: "l"(p), "f"(acc.x), "f"(acc.y), "f"(acc.z), "f"(acc.w) : "memory");
}

// ---------------- fused GRU (both layers, all steps, gi precompute, head) ----------------
__device__ __forceinline__ float sigmoidf_(float x) { return 1.0f / (1.0f + expf(-x)); }

__global__ __launch_bounds__(GATE, 1)
void gru_fused_kernel(const float* __restrict__ Wih0, const float* __restrict__ Whh0,
                      const float* __restrict__ bih0, const float* __restrict__ bhh0,
                      const float* __restrict__ Wih1, const float* __restrict__ Whh1,
                      const float* __restrict__ bih1, const float* __restrict__ bhh1,
                      const float* __restrict__ Wc,   const float* __restrict__ bc,
                      float* __restrict__ out) {
    int g = blockIdx.x;
    int j = threadIdx.x;

    __shared__ float emb_s[T_][FF];
    __shared__ float gi_s[T_][GATE];
    __shared__ float outs_s[T_][FF];
    __shared__ float h_s[FF];
    __shared__ float gates_s[GATE];

    for (int i = j; i < T_*FF; i += GATE) {
        int t = i / FF, f = i - t*FF;
        float c = (float)g_cntI[t*GG + g];
        emb_s[t][f] = g_pool[(size_t)(t*GG + g)*FF + f] / fmaxf(c, 1.0f);
    }
    __syncthreads();

    float4 w4[32];

    // Phase A: gi0
    {
        const float4* wr = (const float4*)(Wih0 + (size_t)j*FF);
        #pragma unroll
        for (int i = 0; i < 32; i++) w4[i] = wr[i];
        float bj = bih0[j];
        #pragma unroll
        for (int t = 0; t < T_; t++) {
            const float4* e4 = (const float4*)emb_s[t];
            float acc = bj;
            #pragma unroll
            for (int i = 0; i < 32; i++) {
                float4 ev = e4[i];
                acc += w4[i].x*ev.x + w4[i].y*ev.y + w4[i].z*ev.z + w4[i].w*ev.w;
            }
            gi_s[t][j] = acc;
        }
    }
    if (j < FF) h_s[j] = 0.f;
    __syncthreads();

    // Phase B: layer-0 recurrence
    {
        const float4* wr = (const float4*)(Whh0 + (size_t)j*FF);
        #pragma unroll
        for (int i = 0; i < 32; i++) w4[i] = wr[i];
        float bj = bhh0[j];
        for (int t = 0; t < T_; t++) {
            const float4* h4 = (const float4*)h_s;
            float acc = bj;
            #pragma unroll
            for (int i = 0; i < 32; i++) {
                float4 hv = h4[i];
                acc += w4[i].x*hv.x + w4[i].y*hv.y + w4[i].z*hv.z + w4[i].w*hv.w;
            }
            gates_s[j] = acc;
            __syncthreads();
            if (j < FF) {
                float r = sigmoidf_(gi_s[t][j]        + gates_s[j]);
                float z = sigmoidf_(gi_s[t][FF+j]     + gates_s[FF+j]);
                float n = tanhf   (gi_s[t][2*FF+j]    + r*gates_s[2*FF+j]);
                float hn = (1.0f - z)*n + z*h_s[j];
                h_s[j] = hn;
                outs_s[t][j] = hn;
            }
            __syncthreads();
        }
    }

    // Phase C: gi1
    {
        const float4* wr = (const float4*)(Wih1 + (size_t)j*FF);
        #pragma unroll
        for (int i = 0; i < 32; i++) w4[i] = wr[i];
        float bj = bih1[j];
        #pragma unroll
        for (int t = 0; t < T_; t++) {
            const float4* o4 = (const float4*)outs_s[t];
            float acc = bj;
            #pragma unroll
            for (int i = 0; i < 32; i++) {
                float4 ov = o4[i];
                acc += w4[i].x*ov.x + w4[i].y*ov.y + w4[i].z*ov.z + w4[i].w*ov.w;
            }
            gi_s[t][j] = acc;
        }
    }
    __syncthreads();
    if (j < FF) h_s[j] = 0.f;
    __syncthreads();

    // Phase D: layer-1 recurrence
    {
        const float4* wr = (const float4*)(Whh1 + (size_t)j*FF);
        #pragma unroll
        for (int i = 0; i < 32; i++) w4[i] = wr[i];
        float bj = bhh1[j];
        for (int t = 0; t < T_; t++) {
            const float4* h4 = (const float4*)h_s;
            float acc = bj;
            #pragma unroll
            for (int i = 0; i < 32; i++) {
                float4 hv = h4[i];
                acc += w4[i].x*hv.x + w4[i].y*hv.y + w4[i].z*hv.z + w4[i].w*hv.w;
            }
            gates_s[j] = acc;
            __syncthreads();
            if (j < FF) {
                float r = sigmoidf_(gi_s[t][j]     + gates_s[j]);
                float z = sigmoidf_(gi_s[t][FF+j]  + gates_s[FF+j]);
                float n = tanhf   (gi_s[t][2*FF+j] + r*gates_s[2*FF+j]);
                h_s[j] = (1.0f - z)*n + z*h_s[j];
            }
            __syncthreads();
        }
    }

    // Phase E: head
    if (j < CC) {
        const float* wc = Wc + (size_t)j*FF;
        float acc = bc[j];
        #pragma unroll 4
        for (int k = 0; k < FF; k++) acc += h_s[k] * wc[k];
        out[g*CC + j] = acc;
    }
}

// ---------------- launch ----------------
extern "C" void kernel_launch(void* const* d_in, const int* in_sizes, int n_in,
                              void* d_out, int out_size) {
    const float* x     = (const float*)d_in[0];
    const int*   ei    = (const int*)  d_in[1];
    const int*   batch = (const int*)  d_in[2];
    const float* W1    = (const float*)d_in[3];
    const float* b1    = (const float*)d_in[4];
    const float* W2    = (const float*)d_in[5];
    const float* b2    = (const float*)d_in[6];
    const float* Wih0  = (const float*)d_in[7];
    const float* Whh0  = (const float*)d_in[8];
    const float* bih0  = (const float*)d_in[9];
    const float* bhh0  = (const float*)d_in[10];
    const float* Wih1  = (const float*)d_in[11];
    const float* Whh1  = (const float*)d_in[12];
    const float* bih1  = (const float*)d_in[13];
    const float* bhh1  = (const float*)d_in[14];
    const float* Wc    = (const float*)d_in[15];
    const float* bc    = (const float*)d_in[16];
    float* out = (float*)d_out;

    static cudaStream_t s2 = 0;
    static cudaEvent_t evFork = 0, evJoin = 0;
    if (!s2) {
        cudaStreamCreateWithFlags(&s2, cudaStreamNonBlocking);
        cudaEventCreateWithFlags(&evFork, cudaEventDisableTiming);
        cudaEventCreateWithFlags(&evJoin, cudaEventDisableTiming);
        cudaFuncSetAttribute(gemm128_kernel<float>,
                             cudaFuncAttributeMaxDynamicSharedMemorySize, 98304);
        cudaFuncSetAttribute(gemm128_kernel<__half>,
                             cudaFuncAttributeMaxDynamicSharedMemorySize, 98304);
    }

    void* p;
    cudaGetSymbolAddress(&p, g_bufA);  __half* bufA = (__half*)p;
    cudaGetSymbolAddress(&p, g_bufB);  __half* bufB = (__half*)p;

    // fork: GEMM1 on s2, CSR chain on main stream, then join
    cudaEventRecord(evFork, 0);
    cudaStreamWaitEvent(s2, evFork, 0);
    gemm128_kernel<float><<<T_*NN/64, 256, 98304, s2>>>(x, W1, bufA);
    cudaEventRecord(evJoin, s2);

    zero_main_kernel<<<(T_*NN + 255)/256, 256>>>();
    hist_count_kernel<<<(T_*EE + 255)/256, 256>>>(ei, batch);
    scan_kernel<<<T_, 1024>>>();
    fill_kernel<<<(T_*EE + 255)/256, 256>>>(ei);

    cudaStreamWaitEvent(0, evJoin, 0);

    // GCN layer 1 aggregation (fp16 gather)
    agg_kernel<<<(T_*NN*32 + 255)/256, 256>>>(bufA, bufB, b1);
    // GCN layer 2 + fused mean-pool accumulation
    gemm128_kernel<__half><<<T_*NN/64, 256, 98304>>>(bufB, W2, bufA);
    agg_pool_kernel<<<(T_*NN*32 + 255)/256, 256>>>(bufA, b2, batch);

    // fused GRU (2 layers × 8 steps) + head, one launch
    gru_fused_kernel<<<GG, GATE>>>(Wih0, Whh0, bih0, bhh0,
                                   Wih1, Whh1, bih1, bhh1, Wc, bc, out);
}

// round 5
// speedup vs baseline: 2.8355x; 1.6527x over previous
#include <cuda_runtime.h>
#include <cuda_fp16.h>
#include <math.h>

#define T_  8
#define NN  10000
#define EE  160000
#define FF  128
#define GG  32
#define CC  10
#define GATE 384
#define SMP 136   // padded smem row stride (halves)

// ---------------- scratch (static __device__ — no allocations allowed) ----------------
__device__ __align__(16) __half g_bufA[T_*NN*FF];   // fp16 node features
__device__ __align__(16) __half g_bufB[T_*NN*FF];
__device__ __align__(16) __half g_W1t[FF*FF];       // W1^T fp16 [n][k]
__device__ __align__(16) __half g_W2t[FF*FF];       // W2^T fp16 [n][k]
__device__ int   g_rowptr[T_*(NN+1)];
__device__ int   g_cursor[T_*NN];
__device__ int   g_colidx[T_*EE];
__device__ float g_dinv[T_*NN];
__device__ __align__(16) float g_pool[T_*GG*FF];
__device__ int   g_cntI[T_*GG];

// ---------------- zeroing ----------------
__global__ void zero_main_kernel() {
    int idx = blockIdx.x * blockDim.x + threadIdx.x;
    if (idx < T_*NN)     g_cursor[idx] = 0;
    if (idx < T_*GG*FF)  g_pool[idx]   = 0.f;
    if (idx < T_*GG)     g_cntI[idx]   = 0;
}

// ---------------- weight prep: transpose + fp16 ----------------
__global__ void prep_weights_kernel(const float* __restrict__ W1, const float* __restrict__ W2) {
    int idx = blockIdx.x * blockDim.x + threadIdx.x;
    if (idx >= FF*FF) return;
    int k = idx >> 7, n = idx & (FF-1);
    g_W1t[n*FF + k] = __float2half(W1[k*FF + n]);
    g_W2t[n*FF + k] = __float2half(W2[k*FF + n]);
}

// ---------------- CSR build + batch counts ----------------
__global__ void hist_count_kernel(const int* __restrict__ ei, const int* __restrict__ batch) {
    int idx = blockIdx.x * blockDim.x + threadIdx.x;
    if (idx < T_*EE) {
        int t = idx / EE, e = idx - t*EE;
        int dst = ei[(t*2 + 1)*EE + e];
        atomicAdd(&g_cursor[t*NN + dst], 1);
    }
    if (idx < T_*NN) {
        int t = idx / NN;
        int g = batch[idx];
        atomicAdd(&g_cntI[t*GG + g], 1);
    }
}

__global__ void scan_kernel() {
    int t = blockIdx.x;
    __shared__ int warpsums[32];
    __shared__ int carry_s;
    int tid = threadIdx.x;            // 1024
    int lane = tid & 31, wid = tid >> 5;
    if (tid == 0) carry_s = 0;
    __syncthreads();
    for (int base = 0; base < NN; base += 1024) {
        int i = base + tid;
        int v = (i < NN) ? g_cursor[t*NN + i] : 0;
        int inc = v;
        #pragma unroll
        for (int o = 1; o < 32; o <<= 1) {
            int y = __shfl_up_sync(0xFFFFFFFFu, inc, o);
            if (lane >= o) inc += y;
        }
        if (lane == 31) warpsums[wid] = inc;
        __syncthreads();
        if (wid == 0) {
            int w = warpsums[lane];
            #pragma unroll
            for (int o = 1; o < 32; o <<= 1) {
                int y = __shfl_up_sync(0xFFFFFFFFu, w, o);
                if (lane >= o) w += y;
            }
            warpsums[lane] = w;
        }
        __syncthreads();
        int exc = inc - v + (wid ? warpsums[wid-1] : 0);
        int off = carry_s + exc;
        if (i < NN) {
            g_rowptr[t*(NN+1) + i] = off;
            g_cursor[t*NN + i]     = off;
            g_dinv[t*NN + i]       = rsqrtf((float)v + 1.0f);
        }
        __syncthreads();
        if (tid == 1023) carry_s += warpsums[31];
        __syncthreads();
    }
    if (tid == 0) g_rowptr[t*(NN+1) + NN] = carry_s;
}

__global__ void fill_kernel(const int* __restrict__ ei) {
    int idx = blockIdx.x * blockDim.x + threadIdx.x;
    if (idx >= T_*EE) return;
    int t = idx / EE, e = idx - t*EE;
    int src = ei[(t*2 + 0)*EE + e];
    int dst = ei[(t*2 + 1)*EE + e];
    int pos = atomicAdd(&g_cursor[t*NN + dst], 1);
    g_colidx[t*EE + pos] = src;
}

// ---------------- tensor-core GEMM: O[M,128](fp16) = A[M,128] @ W, Wt fp16 [n][k] ----------------
// block 256 thr (8 warps), tile 128 rows x 128 cols, warp: 16 rows x 128 cols
// mma.sync.m16n8k16 f16 x f16 -> f32
template<typename TA>
__global__ __launch_bounds__(256, 1)
void gemm_mma_kernel(const TA* __restrict__ A, const __half* __restrict__ Wt,
                     __half* __restrict__ O) {
    extern __shared__ __half smh[];
    __half* Xs = smh;                 // 128 x SMP
    __half* Ws = smh + 128*SMP;       // 128 x SMP
    int tid = threadIdx.x;
    size_t row0 = (size_t)blockIdx.x * 128;

    // load Wt [n][k] -> Ws
    for (int i = tid; i < 128*16; i += 256) {
        int r = i >> 4, s = i & 15;
        *(uint4*)(Ws + r*SMP + s*8) = *(const uint4*)(Wt + r*FF + s*8);
    }
    // load X rows -> Xs (convert fp32->fp16 if needed)
    if constexpr (sizeof(TA) == 4) {
        const float* Af = (const float*)A;
        for (int i = tid; i < 128*32; i += 256) {
            int r = i >> 5, s = i & 31;
            float4 f = *(const float4*)(Af + (row0 + r)*FF + s*4);
            __half2 h0 = __floats2half2_rn(f.x, f.y);
            __half2 h1 = __floats2half2_rn(f.z, f.w);
            uint2 u; u.x = *(unsigned*)&h0; u.y = *(unsigned*)&h1;
            *(uint2*)(Xs + r*SMP + s*4) = u;
        }
    } else {
        const __half* Ah = (const __half*)A;
        for (int i = tid; i < 128*16; i += 256) {
            int r = i >> 4, s = i & 15;
            *(uint4*)(Xs + r*SMP + s*8) = *(const uint4*)(Ah + (row0 + r)*FF + s*8);
        }
    }
    __syncthreads();

    int w = tid >> 5, lane = tid & 31;
    int g = lane >> 2, t4 = lane & 3;
    float d[16][4];
    #pragma unroll
    for (int nt = 0; nt < 16; nt++)
        #pragma unroll
        for (int i = 0; i < 4; i++) d[nt][i] = 0.f;

    const __half* xr0 = Xs + (w*16 + g)*SMP;
    const __half* xr1 = xr0 + 8*SMP;
    #pragma unroll
    for (int kk = 0; kk < 8; kk++) {
        int k0 = kk*16 + t4*2;
        unsigned a0 = *(const unsigned*)(xr0 + k0);
        unsigned a1 = *(const unsigned*)(xr1 + k0);
        unsigned a2 = *(const unsigned*)(xr0 + k0 + 8);
        unsigned a3 = *(const unsigned*)(xr1 + k0 + 8);
        #pragma unroll
        for (int nt = 0; nt < 16; nt++) {
            const __half* wr = Ws + (nt*8 + g)*SMP + k0;
            unsigned b0 = *(const unsigned*)(wr);
            unsigned b1 = *(const unsigned*)(wr + 8);
            asm volatile(
                "mma.sync.aligned.m16n8k16.row.col.f32.f16.f16.f32 "
                "{%0,%1,%2,%3}, {%4,%5,%6,%7}, {%8,%9}, {%0,%1,%2,%3};"
                : "+f"(d[nt][0]), "+f"(d[nt][1]), "+f"(d[nt][2]), "+f"(d[nt][3])
                : "r"(a0), "r"(a1), "r"(a2), "r"(a3), "r"(b0), "r"(b1));
        }
    }

    __half* o0 = O + (row0 + w*16 + g)*FF;
    __half* o1 = o0 + 8*FF;
    #pragma unroll
    for (int nt = 0; nt < 16; nt++) {
        __half2 h0 = __floats2half2_rn(d[nt][0], d[nt][1]);
        __half2 h1 = __floats2half2_rn(d[nt][2], d[nt][3]);
        *(unsigned*)(o0 + nt*8 + t4*2) = *(unsigned*)&h0;
        *(unsigned*)(o1 + nt*8 + t4*2) = *(unsigned*)&h1;
    }
}

// ---------------- shared edge-gather body (one warp per (t,node)), fp16 rows ----------------
__device__ __forceinline__ float4 ld_h4(const __half* __restrict__ p) {
    uint2 u = *(const uint2*)p;
    float2 a = __half22float2(*(const __half2*)&u.x);
    float2 b = __half22float2(*(const __half2*)&u.y);
    return make_float4(a.x, a.y, b.x, b.y);
}

__device__ __forceinline__ float4 gather_node(const __half* __restrict__ hbase,
                                              const float* __restrict__ dv_t,
                                              const int* __restrict__ ci,
                                              int beg, int end, int v, float dv, int lane) {
    float4 acc = make_float4(0.f, 0.f, 0.f, 0.f);
    int e = beg;
    for (; e + 4 <= end; e += 4) {
        int s0 = ci[e], s1 = ci[e+1], s2 = ci[e+2], s3 = ci[e+3];
        float c0 = dv * dv_t[s0], c1 = dv * dv_t[s1];
        float c2 = dv * dv_t[s2], c3 = dv * dv_t[s3];
        float4 a0 = ld_h4(hbase + (size_t)s0*FF + lane*4);
        float4 a1 = ld_h4(hbase + (size_t)s1*FF + lane*4);
        float4 a2 = ld_h4(hbase + (size_t)s2*FF + lane*4);
        float4 a3 = ld_h4(hbase + (size_t)s3*FF + lane*4);
        acc.x += c0*a0.x + c1*a1.x + c2*a2.x + c3*a3.x;
        acc.y += c0*a0.y + c1*a1.y + c2*a2.y + c3*a3.y;
        acc.z += c0*a0.z + c1*a1.z + c2*a2.z + c3*a3.z;
        acc.w += c0*a0.w + c1*a1.w + c2*a2.w + c3*a3.w;
    }
    for (; e < end; e++) {
        int s = ci[e];
        float c = dv * dv_t[s];
        float4 hv = ld_h4(hbase + (size_t)s*FF + lane*4);
        acc.x += c*hv.x; acc.y += c*hv.y; acc.z += c*hv.z; acc.w += c*hv.w;
    }
    {   // self-loop
        float c = dv*dv;
        float4 hv = ld_h4(hbase + (size_t)v*FF + lane*4);
        acc.x += c*hv.x; acc.y += c*hv.y; acc.z += c*hv.z; acc.w += c*hv.w;
    }
    return acc;
}

// layer-1 aggregation: write full node features (fp16)
__global__ void agg_kernel(const __half* __restrict__ hin, __half* __restrict__ hout,
                           const float* __restrict__ bias) {
    int wid  = (blockIdx.x * blockDim.x + threadIdx.x) >> 5;
    int lane = threadIdx.x & 31;
    if (wid >= T_*NN) return;
    int t = wid / NN, v = wid - t*NN;
    const float* dv_t = g_dinv + t*NN;
    float dv = dv_t[v];
    int beg = g_rowptr[t*(NN+1) + v];
    int end = g_rowptr[t*(NN+1) + v + 1];
    float4 acc = gather_node(hin + (size_t)t*NN*FF, dv_t, g_colidx + t*EE, beg, end, v, dv, lane);
    float4 b = *(const float4*)(bias + lane*4);
    acc.x = fmaxf(acc.x + b.x, 0.f);
    acc.y = fmaxf(acc.y + b.y, 0.f);
    acc.z = fmaxf(acc.z + b.z, 0.f);
    acc.w = fmaxf(acc.w + b.w, 0.f);
    __half2 h0 = __floats2half2_rn(acc.x, acc.y);
    __half2 h1 = __floats2half2_rn(acc.z, acc.w);
    uint2 u; u.x = *(unsigned*)&h0; u.y = *(unsigned*)&h1;
    *(uint2*)(hout + (size_t)t*NN*FF + (size_t)v*FF + lane*4) = u;
}

// layer-2 aggregation fused with mean-pool accumulation (vector fp32 red atomics)
__global__ void agg_pool_kernel(const __half* __restrict__ hin,
                                const float* __restrict__ bias,
                                const int* __restrict__ batch) {
    int wid  = (blockIdx.x * blockDim.x + threadIdx.x) >> 5;
    int lane = threadIdx.x & 31;
    if (wid >= T_*NN) return;
    int t = wid / NN, v = wid - t*NN;
    const float* dv_t = g_dinv + t*NN;
    float dv = dv_t[v];
    int beg = g_rowptr[t*(NN+1) + v];
    int end = g_rowptr[t*(NN+1) + v + 1];
    float4 acc = gather_node(hin + (size_t)t*NN*FF, dv_t, g_colidx + t*EE, beg, end, v, dv, lane);
    float4 b = *(const float4*)(bias + lane*4);
    acc.x = fmaxf(acc.x + b.x, 0.f);
    acc.y = fmaxf(acc.y + b.y, 0.f);
    acc.z = fmaxf(acc.z + b.z, 0.f);
    acc.w = fmaxf(acc.w + b.w, 0.f);
    int g = batch[t*NN + v];
    float* p = g_pool + (size_t)(t*GG + g)*FF + lane*4;
    asm volatile("red.global.add.v4.f32 [%0], {%1, %2, %3, %4};"
                 :: "l"(p), "f"(acc.x), "f"(acc.y), "f"(acc.z), "f"(acc.w) : "memory");
}

// ---------------- fused GRU (both layers, all steps, gi precompute, head) ----------------
__device__ __forceinline__ float sigmoidf_(float x) { return 1.0f / (1.0f + expf(-x)); }

__global__ __launch_bounds__(GATE, 1)
void gru_fused_kernel(const float* __restrict__ Wih0, const float* __restrict__ Whh0,
                      const float* __restrict__ bih0, const float* __restrict__ bhh0,
                      const float* __restrict__ Wih1, const float* __restrict__ Whh1,
                      const float* __restrict__ bih1, const float* __restrict__ bhh1,
                      const float* __restrict__ Wc,   const float* __restrict__ bc,
                      float* __restrict__ out) {
    int g = blockIdx.x;
    int j = threadIdx.x;

    __shared__ float emb_s[T_][FF];
    __shared__ float gi_s[T_][GATE];
    __shared__ float outs_s[T_][FF];
    __shared__ float h_s[FF];
    __shared__ float gates_s[GATE];

    for (int i = j; i < T_*FF; i += GATE) {
        int t = i / FF, f = i - t*FF;
        float c = (float)g_cntI[t*GG + g];
        emb_s[t][f] = g_pool[(size_t)(t*GG + g)*FF + f] / fmaxf(c, 1.0f);
    }
    __syncthreads();

    float4 w4[32];

    // Phase A: gi0
    {
        const float4* wr = (const float4*)(Wih0 + (size_t)j*FF);
        #pragma unroll
        for (int i = 0; i < 32; i++) w4[i] = wr[i];
        float bj = bih0[j];
        #pragma unroll
        for (int t = 0; t < T_; t++) {
            const float4* e4 = (const float4*)emb_s[t];
            float acc = bj;
            #pragma unroll
            for (int i = 0; i < 32; i++) {
                float4 ev = e4[i];
                acc += w4[i].x*ev.x + w4[i].y*ev.y + w4[i].z*ev.z + w4[i].w*ev.w;
            }
            gi_s[t][j] = acc;
        }
    }
    if (j < FF) h_s[j] = 0.f;
    __syncthreads();

    // Phase B: layer-0 recurrence
    {
        const float4* wr = (const float4*)(Whh0 + (size_t)j*FF);
        #pragma unroll
        for (int i = 0; i < 32; i++) w4[i] = wr[i];
        float bj = bhh0[j];
        for (int t = 0; t < T_; t++) {
            const float4* h4 = (const float4*)h_s;
            float acc = bj;
            #pragma unroll
            for (int i = 0; i < 32; i++) {
                float4 hv = h4[i];
                acc += w4[i].x*hv.x + w4[i].y*hv.y + w4[i].z*hv.z + w4[i].w*hv.w;
            }
            gates_s[j] = acc;
            __syncthreads();
            if (j < FF) {
                float r = sigmoidf_(gi_s[t][j]        + gates_s[j]);
                float z = sigmoidf_(gi_s[t][FF+j]     + gates_s[FF+j]);
                float n = tanhf   (gi_s[t][2*FF+j]    + r*gates_s[2*FF+j]);
                float hn = (1.0f - z)*n + z*h_s[j];
                h_s[j] = hn;
                outs_s[t][j] = hn;
            }
            __syncthreads();
        }
    }

    // Phase C: gi1
    {
        const float4* wr = (const float4*)(Wih1 + (size_t)j*FF);
        #pragma unroll
        for (int i = 0; i < 32; i++) w4[i] = wr[i];
        float bj = bih1[j];
        #pragma unroll
        for (int t = 0; t < T_; t++) {
            const float4* o4 = (const float4*)outs_s[t];
            float acc = bj;
            #pragma unroll
            for (int i = 0; i < 32; i++) {
                float4 ov = o4[i];
                acc += w4[i].x*ov.x + w4[i].y*ov.y + w4[i].z*ov.z + w4[i].w*ov.w;
            }
            gi_s[t][j] = acc;
        }
    }
    __syncthreads();
    if (j < FF) h_s[j] = 0.f;
    __syncthreads();

    // Phase D: layer-1 recurrence
    {
        const float4* wr = (const float4*)(Whh1 + (size_t)j*FF);
        #pragma unroll
        for (int i = 0; i < 32; i++) w4[i] = wr[i];
        float bj = bhh1[j];
        for (int t = 0; t < T_; t++) {
            const float4* h4 = (const float4*)h_s;
            float acc = bj;
            #pragma unroll
            for (int i = 0; i < 32; i++) {
                float4 hv = h4[i];
                acc += w4[i].x*hv.x + w4[i].y*hv.y + w4[i].z*hv.z + w4[i].w*hv.w;
            }
            gates_s[j] = acc;
            __syncthreads();
            if (j < FF) {
                float r = sigmoidf_(gi_s[t][j]     + gates_s[j]);
                float z = sigmoidf_(gi_s[t][FF+j]  + gates_s[FF+j]);
                float n = tanhf   (gi_s[t][2*FF+j] + r*gates_s[2*FF+j]);
                h_s[j] = (1.0f - z)*n + z*h_s[j];
            }
            __syncthreads();
        }
    }

    // Phase E: head
    if (j < CC) {
        const float* wc = Wc + (size_t)j*FF;
        float acc = bc[j];
        #pragma unroll 4
        for (int k = 0; k < FF; k++) acc += h_s[k] * wc[k];
        out[g*CC + j] = acc;
    }
}

// ---------------- launch ----------------
extern "C" void kernel_launch(void* const* d_in, const int* in_sizes, int n_in,
                              void* d_out, int out_size) {
    const float* x     = (const float*)d_in[0];
    const int*   ei    = (const int*)  d_in[1];
    const int*   batch = (const int*)  d_in[2];
    const float* W1    = (const float*)d_in[3];
    const float* b1    = (const float*)d_in[4];
    const float* W2    = (const float*)d_in[5];
    const float* b2    = (const float*)d_in[6];
    const float* Wih0  = (const float*)d_in[7];
    const float* Whh0  = (const float*)d_in[8];
    const float* bih0  = (const float*)d_in[9];
    const float* bhh0  = (const float*)d_in[10];
    const float* Wih1  = (const float*)d_in[11];
    const float* Whh1  = (const float*)d_in[12];
    const float* bih1  = (const float*)d_in[13];
    const float* bhh1  = (const float*)d_in[14];
    const float* Wc    = (const float*)d_in[15];
    const float* bc    = (const float*)d_in[16];
    float* out = (float*)d_out;

    const int GEMM_SMEM = 2*128*SMP*2;  // 69632 B

    static cudaStream_t s2 = 0;
    static cudaEvent_t evFork = 0, evJoin = 0;
    if (!s2) {
        cudaStreamCreateWithFlags(&s2, cudaStreamNonBlocking);
        cudaEventCreateWithFlags(&evFork, cudaEventDisableTiming);
        cudaEventCreateWithFlags(&evJoin, cudaEventDisableTiming);
        cudaFuncSetAttribute(gemm_mma_kernel<float>,
                             cudaFuncAttributeMaxDynamicSharedMemorySize, GEMM_SMEM);
        cudaFuncSetAttribute(gemm_mma_kernel<__half>,
                             cudaFuncAttributeMaxDynamicSharedMemorySize, GEMM_SMEM);
    }

    void* p;
    cudaGetSymbolAddress(&p, g_bufA);  __half* bufA = (__half*)p;
    cudaGetSymbolAddress(&p, g_bufB);  __half* bufB = (__half*)p;
    cudaGetSymbolAddress(&p, g_W1t);   __half* w1t  = (__half*)p;
    cudaGetSymbolAddress(&p, g_W2t);   __half* w2t  = (__half*)p;

    // fork: weight prep + GEMM1 on s2; CSR chain on main stream; then join
    cudaEventRecord(evFork, 0);
    cudaStreamWaitEvent(s2, evFork, 0);
    prep_weights_kernel<<<(FF*FF + 255)/256, 256, 0, s2>>>(W1, W2);
    gemm_mma_kernel<float><<<T_*NN/128, 256, GEMM_SMEM, s2>>>(x, w1t, bufA);
    cudaEventRecord(evJoin, s2);

    zero_main_kernel<<<(T_*NN + 255)/256, 256>>>();
    hist_count_kernel<<<(T_*EE + 255)/256, 256>>>(ei, batch);
    scan_kernel<<<T_, 1024>>>();
    fill_kernel<<<(T_*EE + 255)/256, 256>>>(ei);

    cudaStreamWaitEvent(0, evJoin, 0);

    // GCN layer 1 aggregation (fp16 gather)
    agg_kernel<<<(T_*NN*32 + 255)/256, 256>>>(bufA, bufB, b1);
    // GCN layer 2 GEMM (tensor core) + fused mean-pool aggregation
    gemm_mma_kernel<__half><<<T_*NN/128, 256, GEMM_SMEM>>>(bufB, w2t, bufA);
    agg_pool_kernel<<<(T_*NN*32 + 255)/256, 256>>>(bufA, b2, batch);

    // fused GRU (2 layers × 8 steps) + head, one launch
    gru_fused_kernel<<<GG, GATE>>>(Wih0, Whh0, bih0, bhh0,
                                   Wih1, Whh1, bih1, bhh1, Wc, bc, out);
}